// round 10
// baseline (speedup 1.0000x reference)
#include <cuda_runtime.h>
#include <cuda_bf16.h>
#include <math.h>

// ---------------- problem constants ----------------
#define B_SZ   256
#define T_SZ   512
#define HID    300
#define EMB    300
#define VOCAB  50000
#define NCLS   5
#define GATES  1200        // 4*HID
#define PCOLS  2400        // 2*GATES (A-part | B-part)

// recurrence persistent-kernel tiling (2 CTAs per SM)
#define NCTA   240         // 8 bt-groups x 30 u-tiles, 2 CTAs/SM co-resident
#define BT     32          // batch rows per CTA
#define UT     10          // hidden units per CTA
#define RT     40          // 4 gates * UT rows per CTA
#define HHALF  150         // k half
#define HBLK   (BT * HHALF)        // 4800 floats per (bt, khalf) block
#define HBLKB  (HBLK * 4)          // 19200 bytes
#define WSTR   302                 // Wt row stride (floats), conflict-free LDS.64
#define GPSU   44                  // gp row stride in u64 units

typedef unsigned long long u64;
typedef unsigned int u32;

// ---------------- f32x2 packed math (exact fp32 FMA/add semantics) -----------
__device__ __forceinline__ void ffma2(u64& d, u64 a, u64 b) {
    asm("fma.rn.f32x2 %0, %1, %2, %0;" : "+l"(d) : "l"(a), "l"(b));
}
__device__ __forceinline__ u64 add2(u64 a, u64 b) {
    u64 r; asm("add.rn.f32x2 %0, %1, %2;" : "=l"(r) : "l"(a), "l"(b)); return r;
}
__device__ __forceinline__ u64 dup2(float x) {
    u64 r; asm("mov.b64 %0, {%1, %1};" : "=l"(r) : "f"(x)); return r;
}
__device__ __forceinline__ float2 unpack2(u64 v) {
    float2 f; asm("mov.b64 {%0, %1}, %2;" : "=f"(f.x), "=f"(f.y) : "l"(v)); return f;
}

// ---------------- fast activations (MUFU-based) ------------------------------
__device__ __forceinline__ float fsig(float x) {
    return __fdividef(1.f, 1.f + __expf(-x));
}

// ---------------- static device scratch (no allocations allowed) -------------
__device__ float d_P[(long long)VOCAB * PCOLS];      // 480 MB: glove @ [A|B]^T
__device__ float d_Wcat[PCOLS * EMB];                // repacked W_ih
// h exchange buffer: [parity][khalf][bt][32][150] (contiguous 19200B blocks)
__device__ __align__(256) float d_hx[2 * 2 * 8 * HBLK];
__device__ float d_hsum[B_SZ * HID];                 // sum_t h_t
__device__ u32 d_arrive[8][32];                      // per-bt-group flags (30 used)

// ---------------- prep: repack W_ih, zero h-exchange, reset flags ------------
__global__ void prep_kernel(const float* __restrict__ W_ih,
                            float* __restrict__ Wcat,
                            float* __restrict__ hx) {
    int i = blockIdx.x * blockDim.x + threadIdx.x;
    if (i < PCOLS * EMB) {
        int n = i / EMB, k = i % EMB;
        Wcat[i] = (n < GATES) ? W_ih[n * 600 + k]
                              : W_ih[(n - GATES) * 600 + 300 + k];
    }
    if (i < 2 * 2 * 8 * HBLK) hx[i] = 0.f;
    if (i < 256) ((u32*)d_arrive)[i] = 0u;
}

// ---------------- C = A @ B^T with packed f32x2 FMA (verified R5-R9) ----------
#define TILE 128
#define KB   10
__global__ __launch_bounds__(256)
void sgemm_f2(const float* __restrict__ A, const float* __restrict__ B,
              float* __restrict__ C,
              int M, int N, int Klen, int lda, int ldb, int ldc) {
    __shared__ __align__(16) float As[KB][TILE + 4];
    __shared__ __align__(16) float Bs[KB][TILE + 4];

    const int m0 = blockIdx.y * TILE;
    const int n0 = blockIdx.x * TILE;
    const int tid = threadIdx.x;
    const int tx = tid & 15;
    const int ty = tid >> 4;

    u64 acc[8][4];
#pragma unroll
    for (int i = 0; i < 8; i++)
#pragma unroll
        for (int p = 0; p < 4; p++) acc[i][p] = 0ULL;

    for (int kk = 0; kk < Klen; kk += KB) {
#pragma unroll
        for (int it = 0; it < (TILE * KB) / 256; it++) {
            int idx = tid + it * 256;
            int k = idx % KB;
            int m = idx / KB;
            int gm = m0 + m;
            float v = 0.f;
            if (gm < M) v = A[(long long)gm * lda + (kk + k)];
            As[k][m] = v;
        }
#pragma unroll
        for (int it = 0; it < (TILE * KB) / 256; it++) {
            int idx = tid + it * 256;
            int k = idx % KB;
            int n = idx / KB;
            int gn = n0 + n;
            float v = 0.f;
            if (gn < N) v = B[(long long)gn * ldb + (kk + k)];
            Bs[k][n] = v;
        }
        __syncthreads();

#pragma unroll
        for (int kb = 0; kb < KB; kb++) {
            u64 ad[8], bd[4];
#pragma unroll
            for (int i = 0; i < 8; i++) ad[i] = dup2(As[kb][ty * 8 + i]);
#pragma unroll
            for (int p = 0; p < 4; p++)
                bd[p] = *(const u64*)&Bs[kb][2 * tx + 32 * p];
#pragma unroll
            for (int i = 0; i < 8; i++)
#pragma unroll
                for (int p = 0; p < 4; p++)
                    ffma2(acc[i][p], ad[i], bd[p]);
        }
        __syncthreads();
    }

#pragma unroll
    for (int i = 0; i < 8; i++) {
        int gm = m0 + ty * 8 + i;
        if (gm < M) {
#pragma unroll
            for (int p = 0; p < 4; p++) {
                int gn = n0 + 2 * tx + 32 * p;
                if (gn < N)
                    *(u64*)&C[(long long)gm * ldc + gn] = acc[i][p];
            }
        }
    }
}

// ---------------- acquire/release + TMA helpers -------------------------------
__device__ __forceinline__ u32 ld_acq(const u32* p) {
    u32 v;
    asm volatile("ld.global.acquire.gpu.u32 %0, [%1];" : "=r"(v) : "l"(p));
    return v;
}
__device__ __forceinline__ void st_rel(u32* p, u32 v) {
    asm volatile("st.global.release.gpu.u32 [%0], %1;" :: "l"(p), "r"(v));
}
__device__ __forceinline__ u32 smem_u32(const void* p) {
    u32 a;
    asm("{ .reg .u64 t; cvta.to.shared.u64 t, %1; cvt.u32.u64 %0, t; }"
        : "=r"(a) : "l"(p));
    return a;
}
__device__ __forceinline__ void mbar_init(u32 mbar, u32 cnt) {
    asm volatile("mbarrier.init.shared.b64 [%0], %1;" :: "r"(mbar), "r"(cnt) : "memory");
}
__device__ __forceinline__ void mbar_expect_tx(u32 mbar, u32 bytes) {
    asm volatile("mbarrier.arrive.expect_tx.shared.b64 _, [%0], %1;"
                 :: "r"(mbar), "r"(bytes) : "memory");
}
__device__ __forceinline__ void bulk_cp_g2s(u32 dst, const void* src, u32 bytes, u32 mbar) {
    asm volatile("cp.async.bulk.shared::cluster.global.mbarrier::complete_tx::bytes "
                 "[%0], [%1], %2, [%3];"
                 :: "r"(dst), "l"(src), "r"(bytes), "r"(mbar) : "memory");
}
__device__ __forceinline__ void mbar_wait(u32 mbar, u32 parity) {
    asm volatile(
        "{\n\t.reg .pred P;\n\t"
        "W_%=:\n\t"
        "mbarrier.try_wait.parity.acquire.cta.shared::cta.b64 P, [%0], %1;\n\t"
        "@!P bra W_%=;\n\t}"
        :: "r"(mbar), "r"(parity) : "memory");
}

// ---------------- persistent recurrence kernel --------------------------------
// 240 CTAs x 256 threads, 2 CTAs per SM (stall-hiding via co-residency).
// Per CTA per step: GEMM 32b x 40r x 300k (8 warps = 2 kz x 4 b-octets,
// thread tile 2b x 5r, k-pair f32x2), fused pointwise, warp0 barrier + TMA.
#define SM_WT   (RT * WSTR)                 // 12080 floats
#define SM_H    (2 * HBLK)                  // 9600 floats (lo | hi)
#define SM_GPU  (2 * BT * GPSU)             // 2816 u64
#define SM_FLOATS (SM_WT + SM_H + 2 * SM_GPU)   // 27312
#define SM_BYTES  (SM_FLOATS * 4 + 16)          // 109264 + mbarriers

__global__ __launch_bounds__(256, 2)
void lstm_persistent(const float* __restrict__ W_hh,
                     const float* __restrict__ P,
                     const int* __restrict__ ids,
                     const float* __restrict__ b_ih,
                     const float* __restrict__ b_hh,
                     float* __restrict__ hx,
                     float* __restrict__ hsum) {
    extern __shared__ __align__(16) float sm[];
    float* Wt   = sm;                        // [40][302] r-major, k contiguous
    float* hsm  = sm + SM_WT;                // [2 khalf][32][150]
    u64*   gp64 = (u64*)(hsm + SM_H);        // [2 kz][32][44]

    const int tid = threadIdx.x;
    const int bt  = blockIdx.x & 7;          // bt-group (8 groups)
    const int ut  = blockIdx.x >> 3;         // 0..29
    const int b0c = bt * BT;
    const int u0  = ut * UT;

    const u32 hsm_s = smem_u32(hsm);
    const u32 mbar_lo = smem_u32(sm) + SM_FLOATS * 4;
    const u32 mbar_hi = mbar_lo + 8;

    if (tid == 0) { mbar_init(mbar_lo, 1); mbar_init(mbar_hi, 1); }

    // ---- load this CTA's 40 W_hh rows into smem, r-major (k contiguous) ----
    for (int idx = tid; idx < RT * HID; idx += 256) {
        int r = idx / HID;
        int k = idx - r * HID;
        int g = r / UT;
        int du = r - g * UT;
        Wt[r * WSTR + k] = W_hh[(g * HID + u0 + du) * HID + k];
    }

    // ---- GEMM mapping: 8 warps = 2 kz x 4 b-octets ----
    const int lane = tid & 31;
    const int wrp  = tid >> 5;
    const int kz   = wrp & 1;                // k half: [0,150) or [150,300)
    const int bo   = (wrp >> 1) * 8;         // b octet base: 0,8,16,24
    const int gtx  = lane & 3;               // b = bo + gtx + 4i, i<2
    const int gty  = lane >> 2;              // r = gty*5 + q, q<5  (covers 40)
    const u32 my_mbar = kz ? mbar_hi : mbar_lo;

    // ---- pointwise ownership: 320 cells -> cell tid, cell tid+256 (tid<64) --
    int bl[2], duc[2], hoff[2];
    bool actc[2];
#pragma unroll
    for (int c = 0; c < 2; c++) {
        int cell = tid + c * 256;
        bl[c] = cell / UT;
        duc[c] = cell - bl[c] * UT;
        actc[c] = (c == 0) || (tid < 64);
        int u = u0 + duc[c];
        int kh = (u >= HHALF);
        hoff[c] = ((kh * 8 + bt) * BT + bl[c]) * HHALF + (u - kh * HHALF);
    }
    float cr[2] = {0.f, 0.f};
    float hs[2] = {0.f, 0.f};
    float bs[2][4];
#pragma unroll
    for (int c = 0; c < 2; c++) {
#pragma unroll
        for (int g = 0; g < 4; g++) {
            int col = g * HID + u0 + duc[c];
            bs[c][g] = actc[c] ? (b_ih[col] + b_hh[col]) : 0.f;
        }
    }

    __syncthreads();

    // ---- initial TMAs: parity-0 h (zeroed by prep) ----
    if (tid == 0) {
        mbar_expect_tx(mbar_lo, HBLKB);
        bulk_cp_g2s(hsm_s, hx + (long long)bt * HBLK, HBLKB, mbar_lo);
        mbar_expect_tx(mbar_hi, HBLKB);
        bulk_cp_g2s(hsm_s + HBLKB, hx + (long long)(8 + bt) * HBLK,
                    HBLKB, mbar_hi);
    }

    for (int t = 0; t < T_SZ; t++) {
        float* hx_out = hx + ((t + 1) & 1) * (2 * 8 * HBLK);

        // ---- prefetch P gathers into registers (overlaps TMA wait + GEMM) ----
        float pfA[2][4], pfB[2][4];
#pragma unroll
        for (int c = 0; c < 2; c++) {
#pragma unroll
            for (int g = 0; g < 4; g++) { pfA[c][g] = 0.f; pfB[c][g] = 0.f; }
            if (actc[c]) {
                int row = (b0c + bl[c]) * T_SZ;
                if (t != T_SZ - 1) {          // emb[T-1] zeroed (reference quirk)
                    const float* pa = P + (long long)ids[row + t] * PCOLS
                                        + u0 + duc[c];
#pragma unroll
                    for (int g = 0; g < 4; g++) pfA[c][g] = pa[g * HID];
                }
                if (t != 0) {                 // emb_{-1} is zero padding
                    const float* pb = P + (long long)ids[row + t - 1] * PCOLS
                                        + GATES + u0 + duc[c];
#pragma unroll
                    for (int g = 0; g < 4; g++) pfB[c][g] = pb[g * HID];
                }
            }
        }

        // ---- wait only for this warp's k-half ----
        mbar_wait(my_mbar, (u32)(t & 1));

        // ---- gates GEMM: 32b x 40r, k-pair-packed f32x2 ----
        {
            const float* hb = hsm + kz * HBLK + (bo + gtx) * HHALF;
            const float* wb = Wt + (gty * 5) * WSTR + kz * HHALF;
            u64 acc[2][5];
#pragma unroll
            for (int i = 0; i < 2; i++)
#pragma unroll
                for (int q = 0; q < 5; q++) acc[i][q] = 0ULL;

#pragma unroll 5
            for (int p = 0; p < HHALF / 2; p++) {
                int k = 2 * p;
                u64 hd0 = *(const u64*)(hb + k);
                u64 hd1 = *(const u64*)(hb + 4 * HHALF + k);
                u64 wd[5];
#pragma unroll
                for (int q = 0; q < 5; q++)
                    wd[q] = *(const u64*)(wb + q * WSTR + k);
#pragma unroll
                for (int q = 0; q < 5; q++) {
                    ffma2(acc[0][q], hd0, wd[q]);
                    ffma2(acc[1][q], hd1, wd[q]);
                }
            }
            u64* g0 = gp64 + (kz * BT + bo + gtx) * GPSU + gty * 5;
#pragma unroll
            for (int i = 0; i < 2; i++)
#pragma unroll
                for (int q = 0; q < 5; q++)
                    g0[i * 4 * GPSU + q] = acc[i][q];
        }
        __syncthreads();

        // ---- fused cell update: u64 gp reduce + prefetched P + activations --
#pragma unroll
        for (int c = 0; c < 2; c++) {
            if (actc[c]) {
                float g4[4];
#pragma unroll
                for (int g = 0; g < 4; g++) {
                    int r = g * UT + duc[c];
                    u64 s0 = gp64[(0 * BT + bl[c]) * GPSU + r];
                    u64 s1 = gp64[(1 * BT + bl[c]) * GPSU + r];
                    float2 f = unpack2(add2(s0, s1));
                    g4[g] = f.x + f.y + bs[c][g] + pfA[c][g] + pfB[c][g];
                }
                float ig = fsig(g4[0]);
                float fg = fsig(g4[1]);
                float gg = 2.f * fsig(2.f * g4[2]) - 1.f;   // tanh
                float og = fsig(g4[3]);
                cr[c] = fg * cr[c] + ig * gg;
                float hv = og * (2.f * fsig(2.f * cr[c]) - 1.f);
                hx_out[hoff[c]] = hv;
                hs[c] += hv;
            }
        }
        __syncthreads();   // hout written + gp consumed before release/reuse

        // ---- warp0 only: release, poll group (30 uts), issue next TMAs ----
        if (t + 1 < T_SZ && wrp == 0) {
            if (lane == 0) { __threadfence(); st_rel(&d_arrive[bt][ut], (u32)(t + 1)); }
            if (lane < 30) {
                while (ld_acq(&d_arrive[bt][lane]) < (u32)(t + 1)) {}
            }
            __syncwarp();
            if (lane == 0) {
                mbar_expect_tx(mbar_lo, HBLKB);
                bulk_cp_g2s(hsm_s, hx_out + (long long)bt * HBLK,
                            HBLKB, mbar_lo);
                mbar_expect_tx(mbar_hi, HBLKB);
                bulk_cp_g2s(hsm_s + HBLKB, hx_out + (long long)(8 + bt) * HBLK,
                            HBLKB, mbar_hi);
            }
        }
        // warps 1-7 fall through; next iteration's mbar_wait gates them
    }

    // ---- write hidden-state sums for the classifier ----
#pragma unroll
    for (int c = 0; c < 2; c++) {
        if (actc[c])
            hsum[(b0c + bl[c]) * HID + u0 + duc[c]] = hs[c];
    }
}

// ---------------- classifier head: mean-pool -> dense(100) -> dense(5) -> LSM
__global__ void classifier(const float* __restrict__ hsum,
                           const float* __restrict__ W1, const float* __restrict__ b1,
                           const float* __restrict__ W2, const float* __restrict__ b2,
                           float* __restrict__ out) {
    int b = blockIdx.x;
    int tid = threadIdx.x;   // 128
    __shared__ float pooled[HID];
    __shared__ float l1s[100];
    __shared__ float l2s[NCLS];

    for (int i = tid; i < HID; i += blockDim.x)
        pooled[i] = hsum[b * HID + i] * (1.f / (float)T_SZ);
    __syncthreads();

    if (tid < 100) {
        float s = b1[tid];
        const float* wr = W1 + tid * HID;
#pragma unroll 4
        for (int k = 0; k < HID; k++) s = fmaf(pooled[k], wr[k], s);
        l1s[tid] = 1.f / (1.f + expf(-s));
    }
    __syncthreads();

    if (tid < NCLS) {
        float s = b2[tid];
        const float* wr = W2 + tid * 100;
#pragma unroll 4
        for (int k = 0; k < 100; k++) s = fmaf(l1s[k], wr[k], s);
        l2s[tid] = 1.f / (1.f + expf(-s));
    }
    __syncthreads();

    if (tid < NCLS) {
        float m = l2s[0];
#pragma unroll
        for (int j = 1; j < NCLS; j++) m = fmaxf(m, l2s[j]);
        float sum = 0.f;
#pragma unroll
        for (int j = 0; j < NCLS; j++) sum += expf(l2s[j] - m);
        out[b * NCLS + tid] = l2s[tid] - m - logf(sum);
    }
}

// ------------------------------ launch ---------------------------------------
extern "C" void kernel_launch(void* const* d_in, const int* in_sizes, int n_in,
                              void* d_out, int out_size) {
    const int*   ids  = nullptr;
    const float* glove = nullptr, *W_ih = nullptr, *W_hh = nullptr;
    const float* b_ih = nullptr, *b_hh = nullptr;
    const float* W1 = nullptr, *b1 = nullptr, *W2 = nullptr, *b2 = nullptr;

    for (int i = 0; i < n_in; i++) {
        switch (in_sizes[i]) {
            case B_SZ * T_SZ:      ids   = (const int*)d_in[i];   break;
            case VOCAB * EMB:      glove = (const float*)d_in[i]; break;
            case GATES * 600:      W_ih  = (const float*)d_in[i]; break;
            case GATES * HID:      W_hh  = (const float*)d_in[i]; break;
            case GATES:            if (!b_ih) b_ih = (const float*)d_in[i];
                                   else       b_hh = (const float*)d_in[i]; break;
            case 100 * HID:        W1 = (const float*)d_in[i]; break;
            case 100:              b1 = (const float*)d_in[i]; break;
            case NCLS * 100:       W2 = (const float*)d_in[i]; break;
            case NCLS:             b2 = (const float*)d_in[i]; break;
            default: break; // size-1 scalar (max_num_of_words) ignored
        }
    }
    if (!ids || !glove || !W_ih || !W_hh || !b_ih || !b_hh || !W1 || !b1 || !W2 || !b2)
        return;

    float *P, *Wcat, *hx, *hsum;
    cudaGetSymbolAddress((void**)&P,    d_P);
    cudaGetSymbolAddress((void**)&Wcat, d_Wcat);
    cudaGetSymbolAddress((void**)&hx,   d_hx);
    cudaGetSymbolAddress((void**)&hsum, d_hsum);

    static bool attr_done = false;
    if (!attr_done) {
        cudaFuncSetAttribute(lstm_persistent,
                             cudaFuncAttributeMaxDynamicSharedMemorySize,
                             SM_BYTES);
        attr_done = true;
    }

    // 1) repack W_ih, zero h-exchange + flags       [1 node]
    prep_kernel<<<(PCOLS * EMB + 255) / 256, 256>>>(W_ih, Wcat, hx);

    // 2) vocabulary projection P = glove @ Wcat^T   [1 node]
    {
        dim3 grid((PCOLS + TILE - 1) / TILE, (VOCAB + TILE - 1) / TILE, 1);
        sgemm_f2<<<grid, 256>>>(glove, Wcat, P,
                                VOCAB, PCOLS, EMB, EMB, EMB, PCOLS);
    }

    // 3) whole 512-step LSTM, 240 CTAs (2/SM)       [1 node]
    lstm_persistent<<<NCTA, 256, SM_BYTES>>>(
        W_hh, P, ids, b_ih, b_hh, hx, hsum);

    // 4) classifier head                            [1 node]
    classifier<<<B_SZ, 128>>>(hsum, W1, b1, W2, b2, (float*)d_out);
}

// round 11
// speedup vs baseline: 1.0569x; 1.0569x over previous
#include <cuda_runtime.h>
#include <cuda_bf16.h>
#include <math.h>

// ---------------- problem constants ----------------
#define B_SZ   256
#define T_SZ   512
#define HID    300
#define EMB    300
#define VOCAB  50000
#define NCLS   5
#define GATES  1200        // 4*HID
#define PCOLS  2400        // 2*GATES (A-part | B-part)

// shared recurrence tiling constants
#define BT     32          // batch rows per CTA
#define UT     20          // hidden units per CTA
#define RT     80          // 4 gates * UT rows per CTA
#define WSTR   302         // Wt row stride (floats), conflict-free LDS.64
#define GPSU   84          // gp row stride in u64 units

// cluster path
#define CL     15          // cluster size = u-tiles per bt-group
#define NCTA_CL 120        // 8 clusters x 15
#define HCHUNK (BT * UT)           // 640 floats per CTA's h chunk
#define HCHUNKB (HCHUNK * 4)       // 2560 bytes
#define HTOT   (CL * HCHUNK)       // 9600 floats full h per parity

// fallback (R9) path
#define HHALF  150
#define HBLK   (BT * HHALF)        // 4800 floats per (bt, khalf) block
#define HBLKB  (HBLK * 4)          // 19200 bytes

typedef unsigned long long u64;
typedef unsigned int u32;

// ---------------- f32x2 packed math (exact fp32 FMA/add semantics) -----------
__device__ __forceinline__ void ffma2(u64& d, u64 a, u64 b) {
    asm("fma.rn.f32x2 %0, %1, %2, %0;" : "+l"(d) : "l"(a), "l"(b));
}
__device__ __forceinline__ u64 add2(u64 a, u64 b) {
    u64 r; asm("add.rn.f32x2 %0, %1, %2;" : "=l"(r) : "l"(a), "l"(b)); return r;
}
__device__ __forceinline__ u64 dup2(float x) {
    u64 r; asm("mov.b64 %0, {%1, %1};" : "=l"(r) : "f"(x)); return r;
}
__device__ __forceinline__ float2 unpack2(u64 v) {
    float2 f; asm("mov.b64 {%0, %1}, %2;" : "=f"(f.x), "=f"(f.y) : "l"(v)); return f;
}
__device__ __forceinline__ float fsig(float x) {
    return __fdividef(1.f, 1.f + __expf(-x));
}

// ---------------- static device scratch (no allocations allowed) -------------
__device__ float d_P[(long long)VOCAB * PCOLS];      // 480 MB: glove @ [A|B]^T
__device__ float d_Wcat[PCOLS * EMB];                // repacked W_ih
__device__ __align__(256) float d_hx[2 * 2 * 8 * HBLK];  // fallback h exchange
__device__ float d_hsum[B_SZ * HID];                 // sum_t h_t
__device__ u32 d_arrive[8][16];                      // fallback flags

// ---------------- prep: repack W_ih, zero fallback state ---------------------
__global__ void prep_kernel(const float* __restrict__ W_ih,
                            float* __restrict__ Wcat,
                            float* __restrict__ hx) {
    int i = blockIdx.x * blockDim.x + threadIdx.x;
    if (i < PCOLS * EMB) {
        int n = i / EMB, k = i % EMB;
        Wcat[i] = (n < GATES) ? W_ih[n * 600 + k]
                              : W_ih[(n - GATES) * 600 + 300 + k];
    }
    if (i < 2 * 2 * 8 * HBLK) hx[i] = 0.f;
    if (i < 128) ((u32*)d_arrive)[i] = 0u;
}

// ---------------- C = A @ B^T with packed f32x2 FMA (verified R5-R10) ---------
#define TILE 128
#define KB   10
__global__ __launch_bounds__(256)
void sgemm_f2(const float* __restrict__ A, const float* __restrict__ B,
              float* __restrict__ C,
              int M, int N, int Klen, int lda, int ldb, int ldc) {
    __shared__ __align__(16) float As[KB][TILE + 4];
    __shared__ __align__(16) float Bs[KB][TILE + 4];

    const int m0 = blockIdx.y * TILE;
    const int n0 = blockIdx.x * TILE;
    const int tid = threadIdx.x;
    const int tx = tid & 15;
    const int ty = tid >> 4;

    u64 acc[8][4];
#pragma unroll
    for (int i = 0; i < 8; i++)
#pragma unroll
        for (int p = 0; p < 4; p++) acc[i][p] = 0ULL;

    for (int kk = 0; kk < Klen; kk += KB) {
#pragma unroll
        for (int it = 0; it < (TILE * KB) / 256; it++) {
            int idx = tid + it * 256;
            int k = idx % KB;
            int m = idx / KB;
            int gm = m0 + m;
            float v = 0.f;
            if (gm < M) v = A[(long long)gm * lda + (kk + k)];
            As[k][m] = v;
        }
#pragma unroll
        for (int it = 0; it < (TILE * KB) / 256; it++) {
            int idx = tid + it * 256;
            int k = idx % KB;
            int n = idx / KB;
            int gn = n0 + n;
            float v = 0.f;
            if (gn < N) v = B[(long long)gn * ldb + (kk + k)];
            Bs[k][n] = v;
        }
        __syncthreads();

#pragma unroll
        for (int kb = 0; kb < KB; kb++) {
            u64 ad[8], bd[4];
#pragma unroll
            for (int i = 0; i < 8; i++) ad[i] = dup2(As[kb][ty * 8 + i]);
#pragma unroll
            for (int p = 0; p < 4; p++)
                bd[p] = *(const u64*)&Bs[kb][2 * tx + 32 * p];
#pragma unroll
            for (int i = 0; i < 8; i++)
#pragma unroll
                for (int p = 0; p < 4; p++)
                    ffma2(acc[i][p], ad[i], bd[p]);
        }
        __syncthreads();
    }

#pragma unroll
    for (int i = 0; i < 8; i++) {
        int gm = m0 + ty * 8 + i;
        if (gm < M) {
#pragma unroll
            for (int p = 0; p < 4; p++) {
                int gn = n0 + 2 * tx + 32 * p;
                if (gn < N)
                    *(u64*)&C[(long long)gm * ldc + gn] = acc[i][p];
            }
        }
    }
}

// ---------------- sync + TMA helpers ------------------------------------------
__device__ __forceinline__ u32 ld_acq(const u32* p) {
    u32 v;
    asm volatile("ld.global.acquire.gpu.u32 %0, [%1];" : "=r"(v) : "l"(p));
    return v;
}
__device__ __forceinline__ void st_rel(u32* p, u32 v) {
    asm volatile("st.global.release.gpu.u32 [%0], %1;" :: "l"(p), "r"(v));
}
__device__ __forceinline__ u32 smem_u32(const void* p) {
    u32 a;
    asm("{ .reg .u64 t; cvta.to.shared.u64 t, %1; cvt.u32.u64 %0, t; }"
        : "=r"(a) : "l"(p));
    return a;
}
__device__ __forceinline__ void mbar_init(u32 mbar, u32 cnt) {
    asm volatile("mbarrier.init.shared.b64 [%0], %1;" :: "r"(mbar), "r"(cnt) : "memory");
}
__device__ __forceinline__ void mbar_expect_tx(u32 mbar, u32 bytes) {
    asm volatile("mbarrier.arrive.expect_tx.shared.b64 _, [%0], %1;"
                 :: "r"(mbar), "r"(bytes) : "memory");
}
__device__ __forceinline__ void bulk_cp_g2s(u32 dst, const void* src, u32 bytes, u32 mbar) {
    asm volatile("cp.async.bulk.shared::cluster.global.mbarrier::complete_tx::bytes "
                 "[%0], [%1], %2, [%3];"
                 :: "r"(dst), "l"(src), "r"(bytes), "r"(mbar) : "memory");
}
// smem -> peer smem bulk copy, complete_tx on the (cluster-mapped) peer barrier
__device__ __forceinline__ void bulk_cp_s2s(u32 dst_cluster, u32 src_cta,
                                            u32 bytes, u32 mbar_cluster) {
    asm volatile("cp.async.bulk.shared::cluster.shared::cta.mbarrier::complete_tx::bytes "
                 "[%0], [%1], %2, [%3];"
                 :: "r"(dst_cluster), "r"(src_cta), "r"(bytes), "r"(mbar_cluster)
                 : "memory");
}
__device__ __forceinline__ void mbar_wait(u32 mbar, u32 parity) {
    asm volatile(
        "{\n\t.reg .pred P;\n\t"
        "W_%=:\n\t"
        "mbarrier.try_wait.parity.acquire.cta.shared::cta.b64 P, [%0], %1;\n\t"
        "@!P bra W_%=;\n\t}"
        :: "r"(mbar), "r"(parity) : "memory");
}
__device__ __forceinline__ u32 mapa_u32(u32 local_addr, u32 rank) {
    u32 r;
    asm("mapa.shared::cluster.u32 %0, %1, %2;" : "=r"(r) : "r"(local_addr), "r"(rank));
    return r;
}
__device__ __forceinline__ u32 my_cluster_rank() {
    u32 r; asm("mov.u32 %0, %%cluster_ctarank;" : "=r"(r)); return r;
}

// ================== CLUSTER PATH: 8 clusters x 15 CTAs ========================
// h lives only in smem: hsm[parity][ut][b][20]. After pointwise, each CTA
// bulk-copies its 2560B chunk to all 14 peers (complete_tx on peer mbarrier).
// The data flow IS the sync: no flags, no global h, no grid barrier.
#define CLSM_WT   (RT * WSTR)                // 24160 floats
#define CLSM_H    (2 * HTOT)                 // 19200 floats
#define CLSM_GPU  (2 * BT * GPSU)            // 5376 u64 = 10752 floats
#define CLSM_FLOATS (CLSM_WT + CLSM_H + 2 * CLSM_GPU)   // 54112
#define CLSM_BYTES  (CLSM_FLOATS * 4 + 16)              // 216464
#define EXPECT_B    (14 * HCHUNKB)           // 35840 bytes per step

__global__ __launch_bounds__(256, 1)
void lstm_cluster(const float* __restrict__ W_hh,
                  const float* __restrict__ P,
                  const int* __restrict__ ids,
                  const float* __restrict__ b_ih,
                  const float* __restrict__ b_hh,
                  float* __restrict__ hsum) {
    extern __shared__ __align__(16) float sm[];
    float* Wt   = sm;                        // [80][302] r-major, k contiguous
    float* hsm  = sm + CLSM_WT;              // [2][15][32][20]
    u64*   gp64 = (u64*)(hsm + CLSM_H);      // [2 kz][32][84]

    const int tid = threadIdx.x;
    const u32 ut  = my_cluster_rank();       // 0..14 (u-tile within bt-group)
    const int bt  = blockIdx.x / CL;         // 0..7
    const int b0c = bt * BT;
    const int u0  = (int)ut * UT;

    const u32 hsm_s  = smem_u32(hsm);
    const u32 mbar_b = smem_u32(sm) + CLSM_FLOATS * 4;   // mbar[0], mbar[1]

    if (tid == 0) {
        mbar_init(mbar_b, 1);
        mbar_init(mbar_b + 8, 1);
        mbar_expect_tx(mbar_b + 8, EXPECT_B);   // for t=1 data
        mbar_expect_tx(mbar_b,     EXPECT_B);   // for t=2 data
    }

    // ---- load this CTA's 80 W_hh rows into smem, r-major (k contiguous) ----
    for (int idx = tid; idx < RT * HID; idx += 256) {
        int r = idx / HID;
        int k = idx - r * HID;
        int g = r / UT;
        int du = r - g * UT;
        Wt[r * WSTR + k] = W_hh[(g * HID + u0 + du) * HID + k];
    }
    // ---- zero parity-0 h buffer (h0 = 0) ----
    for (int idx = tid; idx < HTOT; idx += 256) hsm[idx] = 0.f;

    // ---- GEMM mapping: 8 warps = 2 kz (warps 0-3 / 4-7) x 4 quads ----
    const int lane = tid & 31;
    const int wrp  = tid >> 5;
    const int kz   = wrp >> 2;               // 0: ut 0..6, 1: ut 7..14
    const int quad = wrp & 3;
    const int bo   = (quad & 1) * 16;
    const int ro   = (quad >> 1) * 40;
    const int gtx  = lane & 3;               // b = bo + gtx + 4i, i<4
    const int gty  = lane >> 2;              // r = ro + gty*5 + q, q<5
    const int ut_lo = kz ? 7 : 0;
    const int ut_hi = kz ? 15 : 7;

    // ---- pointwise ownership: 3 cells per thread ----
    int bl[3], duc[3];
    bool actc[3];
#pragma unroll
    for (int c = 0; c < 3; c++) {
        int cell = tid + c * 256;
        bl[c] = cell / UT;
        duc[c] = cell - bl[c] * UT;
        actc[c] = (c < 2) || (tid < 128);
    }
    float cr[3] = {0.f, 0.f, 0.f};
    float hs[3] = {0.f, 0.f, 0.f};
    float bs[3][4];
#pragma unroll
    for (int c = 0; c < 3; c++) {
#pragma unroll
        for (int g = 0; g < 4; g++) {
            int col = g * HID + u0 + duc[c];
            bs[c][g] = actc[c] ? (b_ih[col] + b_hh[col]) : 0.f;
        }
    }
    __syncthreads();

    // ---- cluster-wide: all mbarriers initialized before any peer sends ----
    asm volatile("barrier.cluster.arrive.aligned;" ::: "memory");
    asm volatile("barrier.cluster.wait.aligned;" ::: "memory");

    for (int t = 0; t < T_SZ; t++) {
        const int cp = t & 1;                // current parity buffer
        const int np = (t + 1) & 1;          // next parity buffer

        // ---- prefetch P gathers into registers (overlaps wait + GEMM) ----
        float pfA[3][4], pfB[3][4];
#pragma unroll
        for (int c = 0; c < 3; c++) {
#pragma unroll
            for (int g = 0; g < 4; g++) { pfA[c][g] = 0.f; pfB[c][g] = 0.f; }
            if (actc[c]) {
                int row = (b0c + bl[c]) * T_SZ;
                if (t != T_SZ - 1) {          // emb[T-1] zeroed (reference quirk)
                    const float* pa = P + (long long)ids[row + t] * PCOLS
                                        + u0 + duc[c];
#pragma unroll
                    for (int g = 0; g < 4; g++) pfA[c][g] = pa[g * HID];
                }
                if (t != 0) {                 // emb_{-1} is zero padding
                    const float* pb = P + (long long)ids[row + t - 1] * PCOLS
                                        + GATES + u0 + duc[c];
#pragma unroll
                    for (int g = 0; g < 4; g++) pfB[c][g] = pb[g * HID];
                }
            }
        }

        // ---- wait for full h(t) (14 peer chunks; own chunk via local STS) ----
        if (t > 0) {
            mbar_wait(mbar_b + cp * 8, (u32)(((t - 1) >> 1) & 1));
            if (tid == 0 && t + 2 < T_SZ)
                mbar_expect_tx(mbar_b + cp * 8, EXPECT_B);  // re-arm for t+2
        }

        // ---- gates GEMM: 32b x 80r x 300k from local smem ----
        {
            const float* hpar = hsm + cp * HTOT;
            u64 acc[4][5];
#pragma unroll
            for (int i = 0; i < 4; i++)
#pragma unroll
                for (int q = 0; q < 5; q++) acc[i][q] = 0ULL;

            for (int uti = ut_lo; uti < ut_hi; uti++) {
                const float* hb = hpar + uti * HCHUNK + (bo + gtx) * UT;
                const float* wb = Wt + (ro + gty * 5) * WSTR + uti * UT;
#pragma unroll
                for (int dp = 0; dp < UT / 2; dp++) {
                    int k2 = 2 * dp;
                    u64 hd[4], wd[5];
#pragma unroll
                    for (int i = 0; i < 4; i++)
                        hd[i] = *(const u64*)(hb + i * 4 * UT + k2);
#pragma unroll
                    for (int q = 0; q < 5; q++)
                        wd[q] = *(const u64*)(wb + q * WSTR + k2);
#pragma unroll
                    for (int i = 0; i < 4; i++)
#pragma unroll
                        for (int q = 0; q < 5; q++)
                            ffma2(acc[i][q], hd[i], wd[q]);
                }
            }
            u64* g0 = gp64 + (kz * BT + bo + gtx) * GPSU + ro + gty * 5;
#pragma unroll
            for (int i = 0; i < 4; i++)
#pragma unroll
                for (int q = 0; q < 5; q++)
                    g0[i * 4 * GPSU + q] = acc[i][q];
        }
        __syncthreads();

        // ---- fused cell update; write h(t+1) into own chunk of hsm[np] ----
        float* hnext = hsm + np * HTOT + (int)ut * HCHUNK;
#pragma unroll
        for (int c = 0; c < 3; c++) {
            if (actc[c]) {
                float g4[4];
#pragma unroll
                for (int g = 0; g < 4; g++) {
                    int r = g * UT + duc[c];
                    u64 s0 = gp64[(0 * BT + bl[c]) * GPSU + r];
                    u64 s1 = gp64[(1 * BT + bl[c]) * GPSU + r];
                    float2 f = unpack2(add2(s0, s1));
                    g4[g] = f.x + f.y + bs[c][g] + pfA[c][g] + pfB[c][g];
                }
                float ig = fsig(g4[0]);
                float fg = fsig(g4[1]);
                float gg = 2.f * fsig(2.f * g4[2]) - 1.f;   // tanh
                float og = fsig(g4[3]);
                cr[c] = fg * cr[c] + ig * gg;
                float hv = og * (2.f * fsig(2.f * cr[c]) - 1.f);
                hnext[bl[c] * UT + duc[c]] = hv;
                hs[c] += hv;
            }
        }
        __syncthreads();   // all STS of h(t+1) chunk complete CTA-wide

        // ---- broadcast own chunk to the 14 peers (async DSMEM bulk) ----
        if (t + 1 < T_SZ && wrp == 0 && lane < CL && lane != (int)ut) {
            asm volatile("fence.proxy.async.shared::cta;" ::: "memory");
            u32 src = hsm_s + (u32)(np * HTOT + (int)ut * HCHUNK) * 4u;
            u32 dst = mapa_u32(src, (u32)lane);
            u32 rmb = mapa_u32(mbar_b + (u32)np * 8u, (u32)lane);
            bulk_cp_s2s(dst, src, HCHUNKB, rmb);
        }
        // fall through; next iteration's mbar_wait gates consumption
    }

    // ---- write hidden-state sums for the classifier ----
#pragma unroll
    for (int c = 0; c < 3; c++) {
        if (actc[c])
            hsum[(b0c + bl[c]) * HID + u0 + duc[c]] = hs[c];
    }
}

// ================== FALLBACK: verbatim R9 kernel (6431 us) ====================
#define SM_WT   (RT * WSTR)
#define SM_H    (2 * HBLK)
#define SM_GPU  (2 * BT * GPSU)
#define SM_FLOATS (SM_WT + SM_H + 2 * SM_GPU)
#define SM_BYTES  (SM_FLOATS * 4 + 16)

__global__ __launch_bounds__(256, 1)
void lstm_fallback(const float* __restrict__ W_hh,
                   const float* __restrict__ P,
                   const int* __restrict__ ids,
                   const float* __restrict__ b_ih,
                   const float* __restrict__ b_hh,
                   float* __restrict__ hx,
                   float* __restrict__ hsum) {
    extern __shared__ __align__(16) float sm[];
    float* Wt   = sm;
    float* hsm  = sm + SM_WT;
    u64*   gp64 = (u64*)(hsm + SM_H);

    const int tid = threadIdx.x;
    const int bt  = blockIdx.x & 7;
    const int ut  = blockIdx.x >> 3;
    const int b0c = bt * BT;
    const int u0  = ut * UT;

    const u32 hsm_s = smem_u32(hsm);
    const u32 mbar_lo = smem_u32(sm) + SM_FLOATS * 4;
    const u32 mbar_hi = mbar_lo + 8;

    if (tid == 0) { mbar_init(mbar_lo, 1); mbar_init(mbar_hi, 1); }

    for (int idx = tid; idx < RT * HID; idx += 256) {
        int r = idx / HID;
        int k = idx - r * HID;
        int g = r / UT;
        int du = r - g * UT;
        Wt[r * WSTR + k] = W_hh[(g * HID + u0 + du) * HID + k];
    }

    const int lane = tid & 31;
    const int wrp  = tid >> 5;
    const int kz   = wrp & 1;
    const int quad = wrp >> 1;
    const int bo   = (quad & 1) * 16;
    const int ro   = (quad >> 1) * 40;
    const int gtx  = lane & 3;
    const int gty  = lane >> 2;
    const u32 my_mbar = kz ? mbar_hi : mbar_lo;

    int bl[3], duc[3], hoff[3];
    bool actc[3];
#pragma unroll
    for (int c = 0; c < 3; c++) {
        int cell = tid + c * 256;
        bl[c] = cell / UT;
        duc[c] = cell - bl[c] * UT;
        actc[c] = (c < 2) || (tid < 128);
        int u = u0 + duc[c];
        int kh = (u >= HHALF);
        hoff[c] = ((kh * 8 + bt) * BT + bl[c]) * HHALF + (u - kh * HHALF);
    }
    float cr[3] = {0.f, 0.f, 0.f};
    float hs[3] = {0.f, 0.f, 0.f};
    float bs[3][4];
#pragma unroll
    for (int c = 0; c < 3; c++) {
#pragma unroll
        for (int g = 0; g < 4; g++) {
            int col = g * HID + u0 + duc[c];
            bs[c][g] = actc[c] ? (b_ih[col] + b_hh[col]) : 0.f;
        }
    }

    __syncthreads();

    if (tid == 0) {
        mbar_expect_tx(mbar_lo, HBLKB);
        bulk_cp_g2s(hsm_s, hx + (long long)bt * HBLK, HBLKB, mbar_lo);
        mbar_expect_tx(mbar_hi, HBLKB);
        bulk_cp_g2s(hsm_s + HBLKB, hx + (long long)(8 + bt) * HBLK,
                    HBLKB, mbar_hi);
    }

    for (int t = 0; t < T_SZ; t++) {
        float* hx_out = hx + ((t + 1) & 1) * (2 * 8 * HBLK);

        float pfA[3][4], pfB[3][4];
#pragma unroll
        for (int c = 0; c < 3; c++) {
#pragma unroll
            for (int g = 0; g < 4; g++) { pfA[c][g] = 0.f; pfB[c][g] = 0.f; }
            if (actc[c]) {
                int row = (b0c + bl[c]) * T_SZ;
                if (t != T_SZ - 1) {
                    const float* pa = P + (long long)ids[row + t] * PCOLS
                                        + u0 + duc[c];
#pragma unroll
                    for (int g = 0; g < 4; g++) pfA[c][g] = pa[g * HID];
                }
                if (t != 0) {
                    const float* pb = P + (long long)ids[row + t - 1] * PCOLS
                                        + GATES + u0 + duc[c];
#pragma unroll
                    for (int g = 0; g < 4; g++) pfB[c][g] = pb[g * HID];
                }
            }
        }

        mbar_wait(my_mbar, (u32)(t & 1));

        {
            const float* hb = hsm + kz * HBLK + (bo + gtx) * HHALF;
            const float* wb = Wt + (ro + gty * 5) * WSTR + kz * HHALF;
            u64 acc[4][5];
#pragma unroll
            for (int i = 0; i < 4; i++)
#pragma unroll
                for (int q = 0; q < 5; q++) acc[i][q] = 0ULL;

#pragma unroll 3
            for (int p = 0; p < HHALF / 2; p++) {
                int k = 2 * p;
                u64 hd[4], wd[5];
#pragma unroll
                for (int i = 0; i < 4; i++)
                    hd[i] = *(const u64*)(hb + i * 4 * HHALF + k);
#pragma unroll
                for (int q = 0; q < 5; q++)
                    wd[q] = *(const u64*)(wb + q * WSTR + k);
#pragma unroll
                for (int i = 0; i < 4; i++)
#pragma unroll
                    for (int q = 0; q < 5; q++)
                        ffma2(acc[i][q], hd[i], wd[q]);
            }
            u64* g0 = gp64 + (kz * BT + bo + gtx) * GPSU + ro + gty * 5;
#pragma unroll
            for (int i = 0; i < 4; i++)
#pragma unroll
                for (int q = 0; q < 5; q++)
                    g0[i * 4 * GPSU + q] = acc[i][q];
        }
        __syncthreads();

#pragma unroll
        for (int c = 0; c < 3; c++) {
            if (actc[c]) {
                float g4[4];
#pragma unroll
                for (int g = 0; g < 4; g++) {
                    int r = g * UT + duc[c];
                    u64 s0 = gp64[(0 * BT + bl[c]) * GPSU + r];
                    u64 s1 = gp64[(1 * BT + bl[c]) * GPSU + r];
                    float2 f = unpack2(add2(s0, s1));
                    g4[g] = f.x + f.y + bs[c][g] + pfA[c][g] + pfB[c][g];
                }
                float ig = fsig(g4[0]);
                float fg = fsig(g4[1]);
                float gg = 2.f * fsig(2.f * g4[2]) - 1.f;
                float og = fsig(g4[3]);
                cr[c] = fg * cr[c] + ig * gg;
                float hv = og * (2.f * fsig(2.f * cr[c]) - 1.f);
                hx_out[hoff[c]] = hv;
                hs[c] += hv;
            }
        }
        __syncthreads();

        if (t + 1 < T_SZ && wrp == 0) {
            if (lane == 0) { __threadfence(); st_rel(&d_arrive[bt][ut], (u32)(t + 1)); }
            if (lane < 15) {
                while (ld_acq(&d_arrive[bt][lane]) < (u32)(t + 1)) {}
            }
            __syncwarp();
            if (lane == 0) {
                mbar_expect_tx(mbar_lo, HBLKB);
                bulk_cp_g2s(hsm_s, hx_out + (long long)bt * HBLK,
                            HBLKB, mbar_lo);
                mbar_expect_tx(mbar_hi, HBLKB);
                bulk_cp_g2s(hsm_s + HBLKB, hx_out + (long long)(8 + bt) * HBLK,
                            HBLKB, mbar_hi);
            }
        }
    }

#pragma unroll
    for (int c = 0; c < 3; c++) {
        if (actc[c])
            hsum[(b0c + bl[c]) * HID + u0 + duc[c]] = hs[c];
    }
}

// ---------------- classifier head: mean-pool -> dense(100) -> dense(5) -> LSM
__global__ void classifier(const float* __restrict__ hsum,
                           const float* __restrict__ W1, const float* __restrict__ b1,
                           const float* __restrict__ W2, const float* __restrict__ b2,
                           float* __restrict__ out) {
    int b = blockIdx.x;
    int tid = threadIdx.x;   // 128
    __shared__ float pooled[HID];
    __shared__ float l1s[100];
    __shared__ float l2s[NCLS];

    for (int i = tid; i < HID; i += blockDim.x)
        pooled[i] = hsum[b * HID + i] * (1.f / (float)T_SZ);
    __syncthreads();

    if (tid < 100) {
        float s = b1[tid];
        const float* wr = W1 + tid * HID;
#pragma unroll 4
        for (int k = 0; k < HID; k++) s = fmaf(pooled[k], wr[k], s);
        l1s[tid] = 1.f / (1.f + expf(-s));
    }
    __syncthreads();

    if (tid < NCLS) {
        float s = b2[tid];
        const float* wr = W2 + tid * 100;
#pragma unroll 4
        for (int k = 0; k < 100; k++) s = fmaf(l1s[k], wr[k], s);
        l2s[tid] = 1.f / (1.f + expf(-s));
    }
    __syncthreads();

    if (tid < NCLS) {
        float m = l2s[0];
#pragma unroll
        for (int j = 1; j < NCLS; j++) m = fmaxf(m, l2s[j]);
        float sum = 0.f;
#pragma unroll
        for (int j = 0; j < NCLS; j++) sum += expf(l2s[j] - m);
        out[b * NCLS + tid] = l2s[tid] - m - logf(sum);
    }
}

// ------------------------------ launch ---------------------------------------
extern "C" void kernel_launch(void* const* d_in, const int* in_sizes, int n_in,
                              void* d_out, int out_size) {
    const int*   ids  = nullptr;
    const float* glove = nullptr, *W_ih = nullptr, *W_hh = nullptr;
    const float* b_ih = nullptr, *b_hh = nullptr;
    const float* W1 = nullptr, *b1 = nullptr, *W2 = nullptr, *b2 = nullptr;

    for (int i = 0; i < n_in; i++) {
        switch (in_sizes[i]) {
            case B_SZ * T_SZ:      ids   = (const int*)d_in[i];   break;
            case VOCAB * EMB:      glove = (const float*)d_in[i]; break;
            case GATES * 600:      W_ih  = (const float*)d_in[i]; break;
            case GATES * HID:      W_hh  = (const float*)d_in[i]; break;
            case GATES:            if (!b_ih) b_ih = (const float*)d_in[i];
                                   else       b_hh = (const float*)d_in[i]; break;
            case 100 * HID:        W1 = (const float*)d_in[i]; break;
            case 100:              b1 = (const float*)d_in[i]; break;
            case NCLS * 100:       W2 = (const float*)d_in[i]; break;
            case NCLS:             b2 = (const float*)d_in[i]; break;
            default: break; // size-1 scalar (max_num_of_words) ignored
        }
    }
    if (!ids || !glove || !W_ih || !W_hh || !b_ih || !b_hh || !W1 || !b1 || !W2 || !b2)
        return;

    float *P, *Wcat, *hx, *hsum;
    cudaGetSymbolAddress((void**)&P,    d_P);
    cudaGetSymbolAddress((void**)&Wcat, d_Wcat);
    cudaGetSymbolAddress((void**)&hx,   d_hx);
    cudaGetSymbolAddress((void**)&hsum, d_hsum);

    cudaFuncSetAttribute(lstm_fallback,
                         cudaFuncAttributeMaxDynamicSharedMemorySize, SM_BYTES);
    cudaFuncSetAttribute(lstm_cluster,
                         cudaFuncAttributeMaxDynamicSharedMemorySize, CLSM_BYTES);
    cudaFuncSetAttribute(lstm_cluster,
                         cudaFuncAttributeNonPortableClusterSizeAllowed, 1);

    // 1) repack W_ih, zero fallback state           [1 node]
    prep_kernel<<<(PCOLS * EMB + 255) / 256, 256>>>(W_ih, Wcat, hx);

    // 2) vocabulary projection P = glove @ Wcat^T   [1 node]
    {
        dim3 grid((PCOLS + TILE - 1) / TILE, (VOCAB + TILE - 1) / TILE, 1);
        sgemm_f2<<<grid, 256>>>(glove, Wcat, P,
                                VOCAB, PCOLS, EMB, EMB, EMB, PCOLS);
    }

    // 3) whole 512-step LSTM: cluster path if 15-CTA clusters fit, else R9
    {
        cudaLaunchConfig_t cfg = {};
        cfg.gridDim = dim3(NCTA_CL, 1, 1);
        cfg.blockDim = dim3(256, 1, 1);
        cfg.dynamicSmemBytes = CLSM_BYTES;
        cfg.stream = 0;
        cudaLaunchAttribute attrs[1];
        attrs[0].id = cudaLaunchAttributeClusterDimension;
        attrs[0].val.clusterDim.x = CL;
        attrs[0].val.clusterDim.y = 1;
        attrs[0].val.clusterDim.z = 1;
        cfg.attrs = attrs;
        cfg.numAttrs = 1;

        int nclu = 0;
        cudaError_t qerr = cudaOccupancyMaxActiveClusters(&nclu, lstm_cluster, &cfg);
        bool use_cluster = (qerr == cudaSuccess && nclu >= 8);
        if (use_cluster) {
            cudaError_t lerr = cudaLaunchKernelEx(&cfg, lstm_cluster,
                                                  W_hh, (const float*)P, ids,
                                                  b_ih, b_hh, hsum);
            if (lerr != cudaSuccess) use_cluster = false;
        }
        if (!use_cluster) {
            cudaGetLastError();   // clear
            lstm_fallback<<<NCTA_CL, 256, SM_BYTES>>>(
                W_hh, P, ids, b_ih, b_hh, hx, hsum);
        }
    }

    // 4) classifier head                            [1 node]
    classifier<<<B_SZ, 128>>>(hsum, W1, b1, W2, b2, (float*)d_out);
}

// round 12
// speedup vs baseline: 1.2117x; 1.1464x over previous
#include <cuda_runtime.h>
#include <cuda_bf16.h>
#include <math.h>

// ---------------- problem constants ----------------
#define B_SZ   256
#define T_SZ   512
#define HID    300
#define EMB    300
#define VOCAB  50000
#define NCLS   5
#define GATES  1200        // 4*HID
#define PCOLS  2400        // 2*GATES (A-part | B-part)

// recurrence tiling: 8 bt-groups x 15 u-tiles = 120 CTAs (1/SM, all resident)
#define BT     32          // batch rows per CTA
#define UT     20          // hidden units per CTA
#define RT     80          // 4 gates * UT rows per CTA
#define WSTR   302         // Wt row stride (floats), conflict-free LDS.64
#define NSLOT  15          // h chunks per step (one per producer CTA)
#define CHF    (BT * UT)   // 640 floats per chunk
#define CHB    (CHF * 4)   // 2560 bytes per chunk
#define NG     5           // chunk groups (3 chunks each), one mbarrier per group
#define GPS2   82          // gp row stride in u64

typedef unsigned long long u64;
typedef unsigned int u32;

// ---------------- f32x2 packed math (exact fp32 FMA/add semantics) -----------
__device__ __forceinline__ void ffma2(u64& d, u64 a, u64 b) {
    asm("fma.rn.f32x2 %0, %1, %2, %0;" : "+l"(d) : "l"(a), "l"(b));
}
__device__ __forceinline__ u64 add2(u64 a, u64 b) {
    u64 r; asm("add.rn.f32x2 %0, %1, %2;" : "=l"(r) : "l"(a), "l"(b)); return r;
}
__device__ __forceinline__ u64 dup2(float x) {
    u64 r; asm("mov.b64 %0, {%1, %1};" : "=l"(r) : "f"(x)); return r;
}
__device__ __forceinline__ float2 unpack2(u64 v) {
    float2 f; asm("mov.b64 {%0, %1}, %2;" : "=f"(f.x), "=f"(f.y) : "l"(v)); return f;
}
__device__ __forceinline__ float fsig(float x) {
    return __fdividef(1.f, 1.f + __expf(-x));
}

// ---------------- static device scratch (no allocations allowed) -------------
__device__ float d_P[(long long)VOCAB * PCOLS];      // 480 MB: glove @ [A|B]^T
__device__ float d_Wcat[PCOLS * EMB];                // repacked W_ih
// h mailbox: [parity][bt][producer ut][32][20]
__device__ __align__(256) float d_hG[2 * 8 * NSLOT * CHF];
__device__ float d_hsum[B_SZ * HID];                 // sum_t h_t
__device__ u32 d_arrive[8][16];                      // per-(bt, producer) flags

// ---------------- prep: repack W_ih, reset flags ------------------------------
__global__ void prep_kernel(const float* __restrict__ W_ih,
                            float* __restrict__ Wcat) {
    int i = blockIdx.x * blockDim.x + threadIdx.x;
    if (i < PCOLS * EMB) {
        int n = i / EMB, k = i % EMB;
        Wcat[i] = (n < GATES) ? W_ih[n * 600 + k]
                              : W_ih[(n - GATES) * 600 + 300 + k];
    }
    if (i < 128) ((u32*)d_arrive)[i] = 0u;
}

// ---------------- C = A @ B^T with packed f32x2 FMA (verified R5-R11) ----------
#define TILE 128
#define KB   10
__global__ __launch_bounds__(256)
void sgemm_f2(const float* __restrict__ A, const float* __restrict__ B,
              float* __restrict__ C,
              int M, int N, int Klen, int lda, int ldb, int ldc) {
    __shared__ __align__(16) float As[KB][TILE + 4];
    __shared__ __align__(16) float Bs[KB][TILE + 4];

    const int m0 = blockIdx.y * TILE;
    const int n0 = blockIdx.x * TILE;
    const int tid = threadIdx.x;
    const int tx = tid & 15;
    const int ty = tid >> 4;

    u64 acc[8][4];
#pragma unroll
    for (int i = 0; i < 8; i++)
#pragma unroll
        for (int p = 0; p < 4; p++) acc[i][p] = 0ULL;

    for (int kk = 0; kk < Klen; kk += KB) {
#pragma unroll
        for (int it = 0; it < (TILE * KB) / 256; it++) {
            int idx = tid + it * 256;
            int k = idx % KB;
            int m = idx / KB;
            int gm = m0 + m;
            float v = 0.f;
            if (gm < M) v = A[(long long)gm * lda + (kk + k)];
            As[k][m] = v;
        }
#pragma unroll
        for (int it = 0; it < (TILE * KB) / 256; it++) {
            int idx = tid + it * 256;
            int k = idx % KB;
            int n = idx / KB;
            int gn = n0 + n;
            float v = 0.f;
            if (gn < N) v = B[(long long)gn * ldb + (kk + k)];
            Bs[k][n] = v;
        }
        __syncthreads();

#pragma unroll
        for (int kb = 0; kb < KB; kb++) {
            u64 ad[8], bd[4];
#pragma unroll
            for (int i = 0; i < 8; i++) ad[i] = dup2(As[kb][ty * 8 + i]);
#pragma unroll
            for (int p = 0; p < 4; p++)
                bd[p] = *(const u64*)&Bs[kb][2 * tx + 32 * p];
#pragma unroll
            for (int i = 0; i < 8; i++)
#pragma unroll
                for (int p = 0; p < 4; p++)
                    ffma2(acc[i][p], ad[i], bd[p]);
        }
        __syncthreads();
    }

#pragma unroll
    for (int i = 0; i < 8; i++) {
        int gm = m0 + ty * 8 + i;
        if (gm < M) {
#pragma unroll
            for (int p = 0; p < 4; p++) {
                int gn = n0 + 2 * tx + 32 * p;
                if (gn < N)
                    *(u64*)&C[(long long)gm * ldc + gn] = acc[i][p];
            }
        }
    }
}

// ---------------- sync + bulk-copy helpers -------------------------------------
__device__ __forceinline__ u32 ld_acq(const u32* p) {
    u32 v;
    asm volatile("ld.global.acquire.gpu.u32 %0, [%1];" : "=r"(v) : "l"(p));
    return v;
}
__device__ __forceinline__ void st_rel(u32* p, u32 v) {
    asm volatile("st.global.release.gpu.u32 [%0], %1;" :: "l"(p), "r"(v));
}
__device__ __forceinline__ u32 smem_u32(const void* p) {
    u32 a;
    asm("{ .reg .u64 t; cvta.to.shared.u64 t, %1; cvt.u32.u64 %0, t; }"
        : "=r"(a) : "l"(p));
    return a;
}
__device__ __forceinline__ void mbar_init(u32 mbar, u32 cnt) {
    asm volatile("mbarrier.init.shared.b64 [%0], %1;" :: "r"(mbar), "r"(cnt) : "memory");
}
__device__ __forceinline__ void mbar_expect_tx(u32 mbar, u32 bytes) {
    asm volatile("mbarrier.arrive.expect_tx.shared.b64 _, [%0], %1;"
                 :: "r"(mbar), "r"(bytes) : "memory");
}
__device__ __forceinline__ void bulk_cp_g2s(u32 dst, const void* src, u32 bytes, u32 mbar) {
    asm volatile("cp.async.bulk.shared::cluster.global.mbarrier::complete_tx::bytes "
                 "[%0], [%1], %2, [%3];"
                 :: "r"(dst), "l"(src), "r"(bytes), "r"(mbar) : "memory");
}
__device__ __forceinline__ void mbar_wait(u32 mbar, u32 parity) {
    asm volatile(
        "{\n\t.reg .pred P;\n\t"
        "W_%=:\n\t"
        "mbarrier.try_wait.parity.acquire.cta.shared::cta.b64 P, [%0], %1;\n\t"
        "@!P bra W_%=;\n\t}"
        :: "r"(mbar), "r"(parity) : "memory");
}
#define BAR_COMPUTE() asm volatile("bar.sync 1, 256;" ::: "memory")

// ---------------- self-timed persistent recurrence kernel ----------------------
// 120 CTAs x 288 threads: 8 compute warps + 1 comm warp. No grid barrier.
// Producers: STG 2.5KB h-chunk + per-chunk release flag.
// Comm warp: lanes 0..14 poll the 15 flags IN PARALLEL, fire one bulk g2s per
// chunk as its flag turns (5 group mbarriers x 3 chunks, double-buffered).
// Compute warps: consume chunk-groups in order; group j has ~j*1.2K cyc slack,
// so producer jitter is absorbed instead of serialized.
#define SM_WT   (RT * WSTR)                    // 24160 floats
#define SM_HS   (2 * NSLOT * CHF)              // 19200 floats
#define SM_GPU  (2 * BT * GPS2)                // 5248 u64
#define SM_FLOATS (SM_WT + SM_HS + 2 * SM_GPU) // 54656... (u64=2 floats)
#define SM_BYTES  (SM_FLOATS * 4 + 128)        // + 10 mbarriers

__global__ __launch_bounds__(288, 1)
void lstm_async(const float* __restrict__ W_hh,
                const float* __restrict__ P,
                const int* __restrict__ ids,
                const float* __restrict__ b_ih,
                const float* __restrict__ b_hh,
                float* __restrict__ hG,
                float* __restrict__ hsum) {
    extern __shared__ __align__(16) float sm[];
    float* Wt   = sm;                          // [80][302] r-major, k contiguous
    float* hsm  = sm + SM_WT;                  // [2][15][32][20]
    u64*   gp64 = (u64*)(hsm + SM_HS);         // [2 kz][32][82]

    const int tid  = threadIdx.x;
    const int lane = tid & 31;
    const int wrp  = tid >> 5;                 // 0..8
    const int bt   = blockIdx.x & 7;
    const int ut   = blockIdx.x >> 3;          // 0..14
    const int b0c  = bt * BT;
    const int u0   = ut * UT;

    const u32 hsm_s   = smem_u32(hsm);
    const u32 mbar_bs = smem_u32(sm) + SM_FLOATS * 4;  // mbar(p,g) = +(p*5+g)*8

    if (tid == 0) {
#pragma unroll
        for (int m = 0; m < 2 * NG; m++) mbar_init(mbar_bs + m * 8, 1);
    }

    // =================== comm warp (warp 8): free-running =====================
    if (wrp == 8) {
        for (int tc = 0; tc < T_SZ - 1; tc++) {      // prepares steps 1..511
            const int np = (tc + 1) & 1;
            // mbar-reuse safety gate: own flag >= tc+1 implies our pointwise(tc)
            // done => our GEMM(tc) done => GEMM(tc-1) (last user of mbar[np])
            // fully consumed. Also needed before reading own chunk via TMA.
            if (lane == 0) {
                while (ld_acq(&d_arrive[bt][ut]) < (u32)(tc + 1)) {}
            }
            __syncwarp();
            if (lane < NG)
                mbar_expect_tx(mbar_bs + (np * NG + lane) * 8, 3 * CHB);
            __syncwarp();
            // fire each chunk's bulk as soon as ITS producer flag turns
            bool done = (lane >= NSLOT);
            while (true) {
                if (!done && ld_acq(&d_arrive[bt][lane]) >= (u32)(tc + 1)) {
                    u32 dst = hsm_s + (u32)(np * NSLOT + lane) * CHB;
                    const float* src = hG +
                        ((size_t)(np * 8 + bt) * NSLOT + lane) * CHF;
                    bulk_cp_g2s(dst, src, CHB,
                                mbar_bs + (np * NG + lane / 3) * 8);
                    done = true;
                }
                if (__all_sync(0xFFFFFFFFu, done)) break;
            }
        }
        return;
    }

    // =================== compute warps (0..7) =================================
    // init: W tile + zero parity-0 h slots (compute threads only)
    for (int idx = tid; idx < RT * HID; idx += 256) {
        int r = idx / HID;
        int k = idx - r * HID;
        int g = r / UT;
        int du = r - g * UT;
        Wt[r * WSTR + k] = W_hh[(g * HID + u0 + du) * HID + k];
    }
    for (int idx = tid; idx < NSLOT * CHF; idx += 256) hsm[idx] = 0.f;

    // GEMM mapping: 8 warps = 2 kz (pairs 0-4 / 5-9 of each chunk) x 4 quads
    const int kz   = wrp & 1;
    const int quad = wrp >> 1;
    const int bo   = (quad & 1) * 16;
    const int ro   = (quad >> 1) * 40;
    const int gtx  = lane & 3;                 // b = bo + gtx + 4i, i<4
    const int gty  = lane >> 2;                // r = ro + gty*5 + q, q<5

    // pointwise ownership: 3 cells per thread
    int bl[3], duc[3];
    bool actc[3];
#pragma unroll
    for (int c = 0; c < 3; c++) {
        int cell = tid + c * 256;
        bl[c] = cell / UT;
        duc[c] = cell - bl[c] * UT;
        actc[c] = (c < 2) || (tid < 128);
    }
    float cr[3] = {0.f, 0.f, 0.f};
    float hs[3] = {0.f, 0.f, 0.f};
    float bs[3][4];
#pragma unroll
    for (int c = 0; c < 3; c++) {
#pragma unroll
        for (int g = 0; g < 4; g++) {
            int col = g * HID + u0 + duc[c];
            bs[c][g] = actc[c] ? (b_ih[col] + b_hh[col]) : 0.f;
        }
    }
    BAR_COMPUTE();   // W + zeroed h slots + mbar init visible to compute warps

    for (int t = 0; t < T_SZ; t++) {
        const int p  = t & 1;
        const int np = (t + 1) & 1;
        const u32 ph = (u32)(((t >> 1) + 1 - p) & 1);

        // ---- prefetch P gathers (overlap chunk waits + GEMM) ----
        float pfA[3][4], pfB[3][4];
#pragma unroll
        for (int c = 0; c < 3; c++) {
#pragma unroll
            for (int g = 0; g < 4; g++) { pfA[c][g] = 0.f; pfB[c][g] = 0.f; }
            if (actc[c]) {
                int row = (b0c + bl[c]) * T_SZ;
                if (t != T_SZ - 1) {           // emb[T-1] zeroed (reference quirk)
                    const float* pa = P + (long long)ids[row + t] * PCOLS
                                        + u0 + duc[c];
#pragma unroll
                    for (int g = 0; g < 4; g++) pfA[c][g] = pa[g * HID];
                }
                if (t != 0) {                  // emb_{-1} is zero padding
                    const float* pb = P + (long long)ids[row + t - 1] * PCOLS
                                        + GATES + u0 + duc[c];
#pragma unroll
                    for (int g = 0; g < 4; g++) pfB[c][g] = pb[g * HID];
                }
            }
        }

        // ---- gates GEMM: 32b x 80r x 300k, chunk-group pipelined ----
        u64 acc[4][5];
#pragma unroll
        for (int i = 0; i < 4; i++)
#pragma unroll
            for (int q = 0; q < 5; q++) acc[i][q] = 0ULL;

        const float* hbase = hsm + p * (NSLOT * CHF);
        for (int g = 0; g < NG; g++) {
            if (t > 0) mbar_wait(mbar_bs + (p * NG + g) * 8, ph);
#pragma unroll
            for (int j3 = 0; j3 < 3; j3++) {
                const int j = g * 3 + j3;
                const float* hb = hbase + j * CHF + (bo + gtx) * UT + kz * 10;
                const float* wb = Wt + (ro + gty * 5) * WSTR + j * UT + kz * 10;
#pragma unroll
                for (int pp = 0; pp < 5; pp++) {
                    int k2 = 2 * pp;
                    u64 hd[4], wd[5];
#pragma unroll
                    for (int i = 0; i < 4; i++)
                        hd[i] = *(const u64*)(hb + i * 4 * UT + k2);
#pragma unroll
                    for (int q = 0; q < 5; q++)
                        wd[q] = *(const u64*)(wb + q * WSTR + k2);
#pragma unroll
                    for (int i = 0; i < 4; i++)
#pragma unroll
                        for (int q = 0; q < 5; q++)
                            ffma2(acc[i][q], hd[i], wd[q]);
                }
            }
        }
        {
            u64* g0 = gp64 + (kz * BT + bo + gtx) * GPS2 + ro + gty * 5;
#pragma unroll
            for (int i = 0; i < 4; i++)
#pragma unroll
                for (int q = 0; q < 5; q++)
                    g0[i * 4 * GPS2 + q] = acc[i][q];
        }
        BAR_COMPUTE();   // gp complete

        // ---- fused cell update; STG own chunk to the mailbox ----
        float* dst = hG + ((size_t)(np * 8 + bt) * NSLOT + ut) * CHF;
#pragma unroll
        for (int c = 0; c < 3; c++) {
            if (actc[c]) {
                float g4[4];
#pragma unroll
                for (int g = 0; g < 4; g++) {
                    int r = g * UT + duc[c];
                    u64 s0 = gp64[(0 * BT + bl[c]) * GPS2 + r];
                    u64 s1 = gp64[(1 * BT + bl[c]) * GPS2 + r];
                    float2 f = unpack2(add2(s0, s1));
                    g4[g] = f.x + f.y + bs[c][g] + pfA[c][g] + pfB[c][g];
                }
                float ig = fsig(g4[0]);
                float fg = fsig(g4[1]);
                float gg = 2.f * fsig(2.f * g4[2]) - 1.f;   // tanh
                float og = fsig(g4[3]);
                cr[c] = fg * cr[c] + ig * gg;
                float hv = og * (2.f * fsig(2.f * cr[c]) - 1.f);
                dst[bl[c] * UT + duc[c]] = hv;   // coalesced (cell == tid + 256c)
                hs[c] += hv;
            }
        }
        BAR_COMPUTE();   // all STGs + gp consumption done (gp reusable)

        // ---- release own chunk (single flag; consumers poll it) ----
        if (tid == 0) {
            __threadfence();
            st_rel(&d_arrive[bt][ut], (u32)(t + 1));
        }
    }

    // ---- write hidden-state sums for the classifier ----
#pragma unroll
    for (int c = 0; c < 3; c++) {
        if (actc[c])
            hsum[(b0c + bl[c]) * HID + u0 + duc[c]] = hs[c];
    }
}

// ---------------- classifier head: mean-pool -> dense(100) -> dense(5) -> LSM
__global__ void classifier(const float* __restrict__ hsum,
                           const float* __restrict__ W1, const float* __restrict__ b1,
                           const float* __restrict__ W2, const float* __restrict__ b2,
                           float* __restrict__ out) {
    int b = blockIdx.x;
    int tid = threadIdx.x;   // 128
    __shared__ float pooled[HID];
    __shared__ float l1s[100];
    __shared__ float l2s[NCLS];

    for (int i = tid; i < HID; i += blockDim.x)
        pooled[i] = hsum[b * HID + i] * (1.f / (float)T_SZ);
    __syncthreads();

    if (tid < 100) {
        float s = b1[tid];
        const float* wr = W1 + tid * HID;
#pragma unroll 4
        for (int k = 0; k < HID; k++) s = fmaf(pooled[k], wr[k], s);
        l1s[tid] = 1.f / (1.f + expf(-s));
    }
    __syncthreads();

    if (tid < NCLS) {
        float s = b2[tid];
        const float* wr = W2 + tid * 100;
#pragma unroll 4
        for (int k = 0; k < 100; k++) s = fmaf(l1s[k], wr[k], s);
        l2s[tid] = 1.f / (1.f + expf(-s));
    }
    __syncthreads();

    if (tid < NCLS) {
        float m = l2s[0];
#pragma unroll
        for (int j = 1; j < NCLS; j++) m = fmaxf(m, l2s[j]);
        float sum = 0.f;
#pragma unroll
        for (int j = 0; j < NCLS; j++) sum += expf(l2s[j] - m);
        out[b * NCLS + tid] = l2s[tid] - m - logf(sum);
    }
}

// ------------------------------ launch ---------------------------------------
extern "C" void kernel_launch(void* const* d_in, const int* in_sizes, int n_in,
                              void* d_out, int out_size) {
    const int*   ids  = nullptr;
    const float* glove = nullptr, *W_ih = nullptr, *W_hh = nullptr;
    const float* b_ih = nullptr, *b_hh = nullptr;
    const float* W1 = nullptr, *b1 = nullptr, *W2 = nullptr, *b2 = nullptr;

    for (int i = 0; i < n_in; i++) {
        switch (in_sizes[i]) {
            case B_SZ * T_SZ:      ids   = (const int*)d_in[i];   break;
            case VOCAB * EMB:      glove = (const float*)d_in[i]; break;
            case GATES * 600:      W_ih  = (const float*)d_in[i]; break;
            case GATES * HID:      W_hh  = (const float*)d_in[i]; break;
            case GATES:            if (!b_ih) b_ih = (const float*)d_in[i];
                                   else       b_hh = (const float*)d_in[i]; break;
            case 100 * HID:        W1 = (const float*)d_in[i]; break;
            case 100:              b1 = (const float*)d_in[i]; break;
            case NCLS * 100:       W2 = (const float*)d_in[i]; break;
            case NCLS:             b2 = (const float*)d_in[i]; break;
            default: break; // size-1 scalar (max_num_of_words) ignored
        }
    }
    if (!ids || !glove || !W_ih || !W_hh || !b_ih || !b_hh || !W1 || !b1 || !W2 || !b2)
        return;

    float *P, *Wcat, *hG, *hsum;
    cudaGetSymbolAddress((void**)&P,    d_P);
    cudaGetSymbolAddress((void**)&Wcat, d_Wcat);
    cudaGetSymbolAddress((void**)&hG,   d_hG);
    cudaGetSymbolAddress((void**)&hsum, d_hsum);

    static bool attr_done = false;
    if (!attr_done) {
        cudaFuncSetAttribute(lstm_async,
                             cudaFuncAttributeMaxDynamicSharedMemorySize,
                             SM_BYTES);
        attr_done = true;
    }

    // 1) repack W_ih + reset flags                  [1 node]
    prep_kernel<<<(PCOLS * EMB + 255) / 256, 256>>>(W_ih, Wcat);

    // 2) vocabulary projection P = glove @ Wcat^T   [1 node]
    {
        dim3 grid((PCOLS + TILE - 1) / TILE, (VOCAB + TILE - 1) / TILE, 1);
        sgemm_f2<<<grid, 256>>>(glove, Wcat, P,
                                VOCAB, PCOLS, EMB, EMB, EMB, PCOLS);
    }

    // 3) whole 512-step LSTM, self-timed dataflow   [1 node]
    lstm_async<<<120, 288, SM_BYTES>>>(W_hh, P, ids, b_ih, b_hh, hG, hsum);

    // 4) classifier head                            [1 node]
    classifier<<<B_SZ, 128>>>(hsum, W1, b1, W2, b2, (float*)d_out);
}